// round 1
// baseline (speedup 1.0000x reference)
#include <cuda_runtime.h>
#include <math.h>

#define N_NODES 50000
#define N_EDGES 800000
#define DIM 128
#define CAP 64

// Scratch (allocation-free rule: __device__ globals)
__device__ float g_support[N_NODES * DIM];       // 25.6 MB
__device__ int   g_cnt[N_NODES];
__device__ int   g_bucket[N_NODES * CAP];        // 12.8 MB
__device__ int   g_ovf[N_EDGES];                 // 3.2 MB (worst case, always correct)
__device__ int   g_ovf_cnt;

// ---------------- K0: zero per-row counters ----------------
__global__ void k_zero() {
    int i = blockIdx.x * blockDim.x + threadIdx.x;
    if (i < N_NODES) g_cnt[i] = 0;
    if (i == 0) g_ovf_cnt = 0;
}

// ---------------- K1: support = X @ W  (FFMA, W smem-resident) ----------------
// Block = 256 threads, 32 rows/block. W loaded in two 64x128 k-chunks (32KB smem),
// X chunk 32x64 (8KB). Each thread: 4 rows x 4 cols accumulators.
__global__ __launch_bounds__(256) void k_gemm(const float* __restrict__ X,
                                              const float* __restrict__ W) {
    __shared__ float Wsm[64 * 128];
    __shared__ float Xsm[32 * 64];
    const int tid    = threadIdx.x;
    const int warpid = tid >> 5;          // 0..7  (row group)
    const int colg   = tid & 31;          // 0..31 (4 cols each)
    const int rbase  = blockIdx.x * 32;

    float4 acc[4];
    acc[0] = acc[1] = acc[2] = acc[3] = make_float4(0.f, 0.f, 0.f, 0.f);

    for (int kc = 0; kc < 128; kc += 64) {
        // load W chunk: 8192 floats = 2048 float4 / 256 thr = 8 each
        const float4* W4 = (const float4*)(W + kc * 128);
        float4* Wsm4 = (float4*)Wsm;
        #pragma unroll
        for (int p = 0; p < 8; p++) Wsm4[tid + p * 256] = W4[tid + p * 256];
        // load X chunk: 32 rows x 16 float4 = 512 float4 / 256 thr = 2 each
        float4* Xsm4 = (float4*)Xsm;
        #pragma unroll
        for (int p = 0; p < 2; p++) {
            int f = tid + p * 256;
            int r = f >> 4, kq = f & 15;
            int row = rbase + r;
            float4 v = make_float4(0.f, 0.f, 0.f, 0.f);
            if (row < N_NODES) v = ((const float4*)X)[row * 32 + (kc >> 2) + kq];
            Xsm4[f] = v;
        }
        __syncthreads();

        #pragma unroll 8
        for (int k = 0; k < 64; k++) {
            float4 w4 = ((const float4*)Wsm)[k * 32 + colg];
            #pragma unroll
            for (int m = 0; m < 4; m++) {
                float x = Xsm[(warpid + 8 * m) * 64 + k];   // warp-uniform broadcast
                acc[m].x += x * w4.x;
                acc[m].y += x * w4.y;
                acc[m].z += x * w4.z;
                acc[m].w += x * w4.w;
            }
        }
        __syncthreads();
    }
    #pragma unroll
    for (int m = 0; m < 4; m++) {
        int row = rbase + warpid + 8 * m;
        if (row < N_NODES)
            ((float4*)g_support)[row * 32 + colg] = acc[m];
    }
}

// ---------------- K2: bucket edges by destination row ----------------
__global__ void k_bucket(const int* __restrict__ rows) {
    int e = blockIdx.x * blockDim.x + threadIdx.x;
    if (e >= N_EDGES) return;
    int r = rows[e];
    int pos = atomicAdd(&g_cnt[r], 1);
    if (pos < CAP) {
        g_bucket[r * CAP + pos] = e;
    } else {
        int o = atomicAdd(&g_ovf_cnt, 1);
        g_ovf[o] = e;   // correct fallback path (expected empty)
    }
}

// ---------------- K3: warp-per-row aggregate + gated residual ----------------
__global__ __launch_bounds__(256) void k_agg(const float* __restrict__ X,
                                             const float* __restrict__ alpha,
                                             const float* __restrict__ vals,
                                             const int* __restrict__ cols,
                                             float* __restrict__ out) {
    int warp = (blockIdx.x * blockDim.x + threadIdx.x) >> 5;
    int lane = threadIdx.x & 31;
    if (warp >= N_NODES) return;

    float a0 = alpha[0], a1 = alpha[1];
    float mx = fmaxf(a0, a1);
    float e0 = __expf(a0 - mx), e1 = __expf(a1 - mx);
    float g0 = e0 / (e0 + e1);          // gate for agg
    float g1 = e1 / (e0 + e1);          // gate for residual input

    float4 x4 = ((const float4*)X)[warp * 32 + lane];
    float4 acc = make_float4(g1 * x4.x, g1 * x4.y, g1 * x4.z, g1 * x4.w);

    int n = g_cnt[warp];
    if (n > CAP) n = CAP;
    const int* bk = g_bucket + warp * CAP;
    for (int j = 0; j < n; j++) {
        int e = bk[j];
        int c = cols[e];
        float v = g0 * vals[e];
        float4 s = ((const float4*)g_support)[c * 32 + lane];
        acc.x += v * s.x;
        acc.y += v * s.y;
        acc.z += v * s.z;
        acc.w += v * s.w;
    }
    ((float4*)out)[warp * 32 + lane] = acc;
}

// ---------------- K3b: overflow fallback (atomicAdd; expected no work) -------
__global__ void k_ovf(const float* __restrict__ alpha,
                      const float* __restrict__ vals,
                      const int* __restrict__ rows,
                      const int* __restrict__ cols,
                      float* __restrict__ out) {
    int nov = g_ovf_cnt;
    if (nov <= 0) return;
    float a0 = alpha[0], a1 = alpha[1];
    float mx = fmaxf(a0, a1);
    float e0 = __expf(a0 - mx), e1 = __expf(a1 - mx);
    float g0 = e0 / (e0 + e1);

    int warp   = (blockIdx.x * blockDim.x + threadIdx.x) >> 5;
    int lane   = threadIdx.x & 31;
    int nwarps = (gridDim.x * blockDim.x) >> 5;
    for (int i = warp; i < nov; i += nwarps) {
        int e = g_ovf[i];
        int r = rows[e], c = cols[e];
        float v = g0 * vals[e];
        #pragma unroll
        for (int q = 0; q < 4; q++)
            atomicAdd(&out[r * DIM + lane * 4 + q],
                      v * g_support[c * DIM + lane * 4 + q]);
    }
}

// ---------------- K4: bias + ELU in place ----------------
__global__ void k_elu(const float* __restrict__ bias, float* __restrict__ out) {
    int i = blockIdx.x * blockDim.x + threadIdx.x;
    if (i >= N_NODES * 32) return;
    float4 b = ((const float4*)bias)[i & 31];
    float4 v = ((float4*)out)[i];
    v.x += b.x; v.y += b.y; v.z += b.z; v.w += b.w;
    v.x = v.x > 0.f ? v.x : expm1f(v.x);
    v.y = v.y > 0.f ? v.y : expm1f(v.y);
    v.z = v.z > 0.f ? v.z : expm1f(v.z);
    v.w = v.w > 0.f ? v.w : expm1f(v.w);
    ((float4*)out)[i] = v;
}

extern "C" void kernel_launch(void* const* d_in, const int* in_sizes, int n_in,
                              void* d_out, int out_size) {
    const float* X     = (const float*)d_in[0];   // inputs  [50000,128]
    const float* W     = (const float*)d_in[1];   // weight  [128,128]
    const float* bias  = (const float*)d_in[2];   // bias    [128]
    const float* alpha = (const float*)d_in[3];   // alpha   [2]
    const float* vals  = (const float*)d_in[4];   // adj_vals [800000]
    const int*   rows  = (const int*)d_in[5];     // adj_rows [800000]
    const int*   cols  = (const int*)d_in[6];     // adj_cols [800000]
    float* out = (float*)d_out;

    k_zero  <<<(N_NODES + 255) / 256, 256>>>();
    k_gemm  <<<(N_NODES + 31) / 32, 256>>>(X, W);
    k_bucket<<<(N_EDGES + 255) / 256, 256>>>(rows);
    k_agg   <<<(N_NODES + 7) / 8, 256>>>(X, alpha, vals, cols, out);
    k_ovf   <<<64, 256>>>(alpha, vals, rows, cols, out);
    k_elu   <<<(N_NODES * 32 + 255) / 256, 256>>>(bias, out);
}

// round 2
// speedup vs baseline: 1.2092x; 1.2092x over previous
#include <cuda_runtime.h>
#include <math.h>

#define N_NODES 50000
#define N_EDGES 800000
#define DIM 128
#define CAP 64

// Scratch (allocation-free rule: __device__ globals)
__device__ float g_support[N_NODES * DIM];       // 25.6 MB
__device__ int   g_cnt[N_NODES];
__device__ int2  g_bucket[N_NODES * CAP];        // 25.6 MB: packed (col, val)
__device__ int   g_ovf[N_EDGES];                 // overflow edge ids (expected empty)
__device__ int   g_ovf_cnt;

// ---------------- K1: support = X @ W  (+ fused counter zeroing) ----------------
// Block = 256 threads, 64 rows/block. 8 rows x 4 cols per thread.
// Per k per thread: 1 LDS.128 (W) + 8 LDS.32 (X bcast) + 32 FFMA -> FFMA-floor bound.
__global__ __launch_bounds__(256) void k_gemm(const float* __restrict__ X,
                                              const float* __restrict__ W) {
    __shared__ float Wsm[64 * 128];   // 32 KB
    __shared__ float Xsm[64 * 64];    // 16 KB
    const int tid    = threadIdx.x;
    const int warpid = tid >> 5;          // 0..7
    const int colg   = tid & 31;          // 0..31 -> 4 cols each
    const int rbase  = blockIdx.x * 64;

    // fused: zero per-row bucket counters (grid covers >= N_NODES threads)
    {
        int g = blockIdx.x * 256 + tid;
        if (g < N_NODES) g_cnt[g] = 0;
        if (g == 0) g_ovf_cnt = 0;
    }

    float4 acc[8];
    #pragma unroll
    for (int m = 0; m < 8; m++) acc[m] = make_float4(0.f, 0.f, 0.f, 0.f);

    for (int kc = 0; kc < 128; kc += 64) {
        // W chunk: 64x128 = 2048 float4 / 256 thr = 8 each
        const float4* W4 = (const float4*)(W + kc * 128);
        float4* Wsm4 = (float4*)Wsm;
        #pragma unroll
        for (int p = 0; p < 8; p++) Wsm4[tid + p * 256] = W4[tid + p * 256];
        // X chunk: 64 rows x 16 float4 = 1024 float4 / 256 thr = 4 each
        float4* Xsm4 = (float4*)Xsm;
        #pragma unroll
        for (int p = 0; p < 4; p++) {
            int f = tid + p * 256;
            int r = f >> 4, kq = f & 15;
            int row = rbase + r;
            float4 v = make_float4(0.f, 0.f, 0.f, 0.f);
            if (row < N_NODES) v = ((const float4*)X)[row * 32 + (kc >> 2) + kq];
            Xsm4[f] = v;
        }
        __syncthreads();

        #pragma unroll 8
        for (int k = 0; k < 64; k++) {
            float4 w4 = ((const float4*)Wsm)[k * 32 + colg];
            #pragma unroll
            for (int m = 0; m < 8; m++) {
                float x = Xsm[(warpid * 8 + m) * 64 + k];   // warp-uniform broadcast
                acc[m].x += x * w4.x;
                acc[m].y += x * w4.y;
                acc[m].z += x * w4.z;
                acc[m].w += x * w4.w;
            }
        }
        __syncthreads();
    }
    #pragma unroll
    for (int m = 0; m < 8; m++) {
        int row = rbase + warpid * 8 + m;
        if (row < N_NODES)
            ((float4*)g_support)[row * 32 + colg] = acc[m];
    }
}

// ---------------- K2: bucket edges by destination row (packed col+val) -------
__global__ void k_bucket(const int* __restrict__ rows,
                         const int* __restrict__ cols,
                         const float* __restrict__ vals) {
    int e = blockIdx.x * blockDim.x + threadIdx.x;
    if (e >= N_EDGES) return;
    int r = rows[e];
    int pos = atomicAdd(&g_cnt[r], 1);
    if (pos < CAP) {
        g_bucket[r * CAP + pos] = make_int2(cols[e], __float_as_int(vals[e]));
    } else {
        int o = atomicAdd(&g_ovf_cnt, 1);
        g_ovf[o] = e;   // correct fallback path (expected empty)
    }
}

// ---------------- K3: warp-per-row aggregate + gated residual + fused ELU ----
__global__ __launch_bounds__(256) void k_agg(const float* __restrict__ X,
                                             const float* __restrict__ alpha,
                                             const float* __restrict__ bias,
                                             float* __restrict__ out) {
    int row  = (blockIdx.x * blockDim.x + threadIdx.x) >> 5;
    int lane = threadIdx.x & 31;
    if (row >= N_NODES) return;

    float a0 = alpha[0], a1 = alpha[1];
    float mx = fmaxf(a0, a1);
    float e0 = __expf(a0 - mx), e1 = __expf(a1 - mx);
    float g0 = e0 / (e0 + e1);          // gate for agg
    float g1 = e1 / (e0 + e1);          // gate for residual input

    float4 x4 = ((const float4*)X)[row * 32 + lane];
    float4 acc = make_float4(g1 * x4.x, g1 * x4.y, g1 * x4.z, g1 * x4.w);

    int n = g_cnt[row];
    if (n > CAP) n = CAP;
    const int2* bk = g_bucket + row * CAP;
    const float4* sup4 = (const float4*)g_support;

    for (int base = 0; base < n; base += 32) {
        // lane-parallel metadata load; invalid lanes -> (c=0, v=0) harmless gather
        int2 meta = make_int2(0, 0);
        if (base + lane < n) meta = bk[base + lane];
        int cnt = n - base; if (cnt > 32) cnt = 32;
        int c4 = (cnt + 3) & ~3;
        for (int j = 0; j < c4; j += 4) {
            int   c0 = __shfl_sync(0xffffffffu, meta.x, j + 0);
            int   c1 = __shfl_sync(0xffffffffu, meta.x, j + 1);
            int   c2 = __shfl_sync(0xffffffffu, meta.x, j + 2);
            int   c3 = __shfl_sync(0xffffffffu, meta.x, j + 3);
            float v0 = g0 * __int_as_float(__shfl_sync(0xffffffffu, meta.y, j + 0));
            float v1 = g0 * __int_as_float(__shfl_sync(0xffffffffu, meta.y, j + 1));
            float v2 = g0 * __int_as_float(__shfl_sync(0xffffffffu, meta.y, j + 2));
            float v3 = g0 * __int_as_float(__shfl_sync(0xffffffffu, meta.y, j + 3));
            float4 s0 = sup4[c0 * 32 + lane];
            float4 s1 = sup4[c1 * 32 + lane];
            float4 s2 = sup4[c2 * 32 + lane];
            float4 s3 = sup4[c3 * 32 + lane];
            acc.x += v0 * s0.x; acc.y += v0 * s0.y; acc.z += v0 * s0.z; acc.w += v0 * s0.w;
            acc.x += v1 * s1.x; acc.y += v1 * s1.y; acc.z += v1 * s1.z; acc.w += v1 * s1.w;
            acc.x += v2 * s2.x; acc.y += v2 * s2.y; acc.z += v2 * s2.z; acc.w += v2 * s2.w;
            acc.x += v3 * s3.x; acc.y += v3 * s3.y; acc.z += v3 * s3.z; acc.w += v3 * s3.w;
        }
    }

    if (g_ovf_cnt == 0) {
        // fused bias + ELU epilogue (normal path)
        float4 b = ((const float4*)bias)[lane];
        acc.x += b.x; acc.y += b.y; acc.z += b.z; acc.w += b.w;
        acc.x = acc.x > 0.f ? acc.x : expm1f(acc.x);
        acc.y = acc.y > 0.f ? acc.y : expm1f(acc.y);
        acc.z = acc.z > 0.f ? acc.z : expm1f(acc.z);
        acc.w = acc.w > 0.f ? acc.w : expm1f(acc.w);
    }
    ((float4*)out)[row * 32 + lane] = acc;
}

// ---------------- K3b: overflow fallback (atomicAdd; expected no work) -------
__global__ void k_ovf(const float* __restrict__ alpha,
                      const float* __restrict__ vals,
                      const int* __restrict__ rows,
                      const int* __restrict__ cols,
                      float* __restrict__ out) {
    int nov = g_ovf_cnt;
    if (nov <= 0) return;
    float a0 = alpha[0], a1 = alpha[1];
    float mx = fmaxf(a0, a1);
    float e0 = __expf(a0 - mx), e1 = __expf(a1 - mx);
    float g0 = e0 / (e0 + e1);

    int warp   = (blockIdx.x * blockDim.x + threadIdx.x) >> 5;
    int lane   = threadIdx.x & 31;
    int nwarps = (gridDim.x * blockDim.x) >> 5;
    for (int i = warp; i < nov; i += nwarps) {
        int e = g_ovf[i];
        int r = rows[e], c = cols[e];
        float v = g0 * vals[e];
        #pragma unroll
        for (int q = 0; q < 4; q++)
            atomicAdd(&out[r * DIM + lane * 4 + q],
                      v * g_support[c * DIM + lane * 4 + q]);
    }
}

// ---------------- K4: bias + ELU (only runs if overflow path was taken) ------
__global__ void k_elu(const float* __restrict__ bias, float* __restrict__ out) {
    if (g_ovf_cnt == 0) return;   // normal path: already applied in k_agg
    int i = blockIdx.x * blockDim.x + threadIdx.x;
    if (i >= N_NODES * 32) return;
    float4 b = ((const float4*)bias)[i & 31];
    float4 v = ((float4*)out)[i];
    v.x += b.x; v.y += b.y; v.z += b.z; v.w += b.w;
    v.x = v.x > 0.f ? v.x : expm1f(v.x);
    v.y = v.y > 0.f ? v.y : expm1f(v.y);
    v.z = v.z > 0.f ? v.z : expm1f(v.z);
    v.w = v.w > 0.f ? v.w : expm1f(v.w);
    ((float4*)out)[i] = v;
}

extern "C" void kernel_launch(void* const* d_in, const int* in_sizes, int n_in,
                              void* d_out, int out_size) {
    const float* X     = (const float*)d_in[0];   // inputs  [50000,128]
    const float* W     = (const float*)d_in[1];   // weight  [128,128]
    const float* bias  = (const float*)d_in[2];   // bias    [128]
    const float* alpha = (const float*)d_in[3];   // alpha   [2]
    const float* vals  = (const float*)d_in[4];   // adj_vals [800000]
    const int*   rows  = (const int*)d_in[5];     // adj_rows [800000]
    const int*   cols  = (const int*)d_in[6];     // adj_cols [800000]
    float* out = (float*)d_out;

    k_gemm  <<<(N_NODES + 63) / 64, 256>>>(X, W);
    k_bucket<<<(N_EDGES + 255) / 256, 256>>>(rows, cols, vals);
    k_agg   <<<(N_NODES + 7) / 8, 256>>>(X, alpha, bias, out);
    k_ovf   <<<64, 256>>>(alpha, vals, rows, cols, out);
    k_elu   <<<(N_NODES * 32 + 255) / 256, 256>>>(bias, out);
}